// round 16
// baseline (speedup 1.0000x reference)
#include <cuda_runtime.h>
#include <math.h>

#define Bz 64
#define Tn 512
#define In 256
#define Hn 1024
#define On 512
#define Gn 4096
#define NSTEPS 100

// packed f32x2 FMA (sm_103a; PTX-only)
#define FMA2(d, a, b) asm("fma.rn.f32x2 %0, %1, %2, %0;" : "+l"(d) : "l"(a), "l"(b))

// ---------------- device scratch (static, allocation-free) ----------------
__device__ float g_h[2][Bz * Hn];
__device__ float g_c[Bz * Hn];
__device__ float g_be[Gn];
__device__ float g_bd[Gn];
__device__ float g_sd[Gn];
__device__ float g_tokf[Bz];
__device__ float g_part[4][Bz * On];

__global__ void prep_kernel(const float* __restrict__ ebih, const float* __restrict__ ebhh,
                            const float* __restrict__ dbih, const float* __restrict__ dbhh,
                            const float* __restrict__ dWih) {
    int i = blockIdx.x * blockDim.x + threadIdx.x;
    if (i < Gn) {
        g_be[i] = ebih[i] + ebhh[i];
        g_bd[i] = dbih[i] + dbhh[i];
        float s = 0.f;
        const float* row = dWih + (size_t)i * On;
        #pragma unroll 8
        for (int j = 0; j < On; j++) s += row[j];
        g_sd[i] = s;
    }
    if (i < Bz * Hn) { g_h[0][i] = 0.f; g_c[i] = 0.f; }
    if (i < Bz) g_tokf[i] = 0.f;
}

__device__ __forceinline__ float sigf(float x) { return 1.f / (1.f + expf(-x)); }

// ---------------------------------------------------------------------------
// Fused LSTM step v5: LDS.128 k-quads + broadcast lane map + double buffering.
// Block = 64 batch x 32 gate cols, grid = 128, 512 threads (2 k-groups of 16k).
// Thread tile: rows {ty,ty+16,ty+32,ty+48} x cols {2tx, 2tx+1}.
// Warp: ty = lane&15 (A conflict-free 16x16B), tx fixed pair (W broadcast).
// Inner loop per 4k: 6x LDS.128 + 16x fma.rn.f32x2.
// ---------------------------------------------------------------------------
#define TSS 36   // tile row stride (words): 16B-aligned, bank-stride 4

template <bool ENC>
__global__ __launch_bounds__(512) void lstm_step(const float* __restrict__ Wih,
                                                 const float* __restrict__ xbase,
                                                 const float* __restrict__ Whh,
                                                 int insel) {
    __shared__ __align__(16) float As[2][64 * TSS];   // [row][k]
    __shared__ __align__(16) float Ws[2][32 * TSS];   // [gate col][k]
    __shared__ float Gp[64 * 32];                     // group-1 partials
    __shared__ float Gs[64 * 33];                     // gates for cell update

    const int tid = threadIdx.x;
    const int sub = tid & 255;
    const int grp = tid >> 8;          // k-half of each 32-k slice
    const int tx = sub >> 4;           // col group (HIGH bits -> W broadcast)
    const int ty = sub & 15;           // row group (LOW bits -> A spread)
    const int col_base = blockIdx.x * 8;
    const int kbase = grp * 16;

    // staging maps (same as v4)
    const int arow = tid >> 3;                 // 0..63
    const int ac0  = (tid & 7) * 4;
    const int wrow = tid >> 3;                 // (tid<256) 0..31
    const int wc   = (tid & 7) * 4;
    const int wgr  = (wrow >> 3) * Hn + col_base + (wrow & 7);

    const float* hin = g_h[insel];
    const int nIn = ENC ? (In / 32) : 0;
    const int nsl = nIn + Hn / 32;

    auto srcA = [&](int s) -> const float* {
        if (ENC && s < nIn)
            return xbase + (size_t)arow * ((long)Tn * In) + s * 32 + ac0;
        return hin + (size_t)arow * Hn + (s - nIn) * 32 + ac0;
    };
    auto srcW = [&](int s) -> const float* {
        if (ENC && s < nIn)
            return Wih + (size_t)wgr * In + s * 32 + wc;
        return Whh + (size_t)wgr * Hn + (s - nIn) * 32 + wc;
    };

    // prologue: stage slice 0 into buffer 0
    {
        *(float4*)&As[0][arow * TSS + ac0] = *(const float4*)srcA(0);
        if (tid < 256)
            *(float4*)&Ws[0][wrow * TSS + wc] = *(const float4*)srcW(0);
    }
    __syncthreads();

    // accumulators: accA = k-pair (0,1) of each quad, accB = pair (2,3)
    unsigned long long accA[4][2] = {}, accB[4][2] = {};

    for (int s = 0; s < nsl; ++s) {
        const int buf = s & 1;
        const bool pre = (s + 1 < nsl);
        float4 va, vw;
        if (pre) {
            va = *(const float4*)srcA(s + 1);
            if (tid < 256) vw = *(const float4*)srcW(s + 1);
        }

        const float* ab = &As[buf][0];
        const float* wb = &Ws[buf][0];
        #pragma unroll
        for (int t = 0; t < 4; ++t) {
            const int kk = kbase + t * 4;
            ulonglong2 w0 = *(const ulonglong2*)&wb[(2 * tx + 0) * TSS + kk];
            ulonglong2 w1 = *(const ulonglong2*)&wb[(2 * tx + 1) * TSS + kk];
            #pragma unroll
            for (int i = 0; i < 4; ++i) {
                ulonglong2 a = *(const ulonglong2*)&ab[(ty + 16 * i) * TSS + kk];
                FMA2(accA[i][0], a.x, w0.x);
                FMA2(accB[i][0], a.y, w0.y);
                FMA2(accA[i][1], a.x, w1.x);
                FMA2(accB[i][1], a.y, w1.y);
            }
        }

        if (pre) {
            *(float4*)&As[buf ^ 1][arow * TSS + ac0] = va;
            if (tid < 256)
                *(float4*)&Ws[buf ^ 1][wrow * TSS + wc] = vw;
        }
        __syncthreads();
    }

    // horizontal reduce: (even,odd) lanes of accA+accB
    float accf[4][2];
    #pragma unroll
    for (int i = 0; i < 4; i++)
        #pragma unroll
        for (int j = 0; j < 2; j++) {
            float lo0, hi0, lo1, hi1;
            asm("mov.b64 {%0,%1}, %2;" : "=f"(lo0), "=f"(hi0) : "l"(accA[i][j]));
            asm("mov.b64 {%0,%1}, %2;" : "=f"(lo1), "=f"(hi1) : "l"(accB[i][j]));
            accf[i][j] = (lo0 + hi0) + (lo1 + hi1);
        }

    // ---- combine group partials (rows = ty + 16*i) ----
    if (grp == 1) {
        #pragma unroll
        for (int i = 0; i < 4; i++)
            #pragma unroll
            for (int j = 0; j < 2; j++)
                Gp[(ty + 16 * i) * 32 + tx * 2 + j] = accf[i][j];
    }
    __syncthreads();

    if (grp == 0) {
        #pragma unroll
        for (int i = 0; i < 4; i++) {
            int r = ty + 16 * i;
            #pragma unroll
            for (int j = 0; j < 2; j++) {
                int oc = tx * 2 + j;
                int gr = (oc >> 3) * Hn + col_base + (oc & 7);
                float g = accf[i][j] + Gp[r * 32 + oc] + (ENC ? g_be[gr] : g_bd[gr]);
                if (!ENC) g += g_tokf[r] * g_sd[gr];   // rank-1 token-input term
                Gs[r * 33 + oc] = g;
            }
        }
    }
    __syncthreads();

    // ---- cell update: 512 (b, hc) pairs, one per thread ----
    const int outsel = insel ^ 1;
    {
        int b = tid >> 3;
        int hc = tid & 7;
        float gi = Gs[b * 33 + hc];
        float gf = Gs[b * 33 + 8 + hc];
        float gg = Gs[b * 33 + 16 + hc];
        float go = Gs[b * 33 + 24 + hc];
        int col = col_base + hc;
        float cprev = g_c[b * Hn + col];
        float cc = sigf(gf) * cprev + sigf(gi) * tanhf(gg);
        g_c[b * Hn + col] = cc;
        g_h[outsel][b * Hn + col] = sigf(go) * tanhf(cc);
    }
}

// fc partial GEMM: grid (32 oc-tiles of 16, 4 K-quarters), 256 threads.
__global__ __launch_bounds__(256) void fc_partial(const float* __restrict__ fcW, int hsel) {
    __shared__ float Ah[64 * 36];
    __shared__ float Wf[16 * 33];
    const int tid = threadIdx.x;
    const int tx = tid & 15;   // one output col each
    const int ty = tid >> 4;   // 4 batch rows each
    const int oc0 = blockIdx.x * 16;
    const int kq = blockIdx.y;
    const float* hin = g_h[hsel];
    float acc[4] = {};

    for (int k0 = kq * 256; k0 < kq * 256 + 256; k0 += 32) {
        {
            int row = tid >> 2;
            int c0 = (tid & 3) * 8;
            const float* src = hin + (size_t)row * Hn + k0 + c0;
            *(float4*)&Ah[row * 36 + c0]     = *(const float4*)(src);
            *(float4*)&Ah[row * 36 + c0 + 4] = *(const float4*)(src + 4);
        }
        if (tid < 128) {
            int wrow = tid >> 3;
            int wc = (tid & 7) * 4;
            float4 v = *(const float4*)(fcW + (size_t)(oc0 + wrow) * Hn + k0 + wc);
            Wf[wrow * 33 + wc + 0] = v.x;
            Wf[wrow * 33 + wc + 1] = v.y;
            Wf[wrow * 33 + wc + 2] = v.z;
            Wf[wrow * 33 + wc + 3] = v.w;
        }
        __syncthreads();
        #pragma unroll
        for (int kk = 0; kk < 32; ++kk) {
            float b = Wf[tx * 33 + kk];
            acc[0] += Ah[(ty * 4 + 0) * 36 + kk] * b;
            acc[1] += Ah[(ty * 4 + 1) * 36 + kk] * b;
            acc[2] += Ah[(ty * 4 + 2) * 36 + kk] * b;
            acc[3] += Ah[(ty * 4 + 3) * 36 + kk] * b;
        }
        __syncthreads();
    }
    #pragma unroll
    for (int i = 0; i < 4; i++)
        g_part[kq][(size_t)(ty * 4 + i) * On + oc0 + tx] = acc[i];
}

// argmax per batch row, first-index tie-break (matches jnp.argmax). f32 output.
__global__ __launch_bounds__(128) void argmax_kernel(const float* __restrict__ fcb,
                                                     float* __restrict__ out, int step) {
    const int b = blockIdx.x;
    const int tid = threadIdx.x;
    __shared__ float sv[128];
    __shared__ int si[128];
    float bestv = -3.4e38f;
    int besti = 0;
    for (int o = tid; o < On; o += 128) {
        float v = fcb[o] + g_part[0][(size_t)b * On + o] + g_part[1][(size_t)b * On + o]
                         + g_part[2][(size_t)b * On + o] + g_part[3][(size_t)b * On + o];
        if (v > bestv) { bestv = v; besti = o; }   // ascending o => first index kept
    }
    sv[tid] = bestv;
    si[tid] = besti;
    __syncthreads();
    for (int s = 64; s > 0; s >>= 1) {
        if (tid < s) {
            float v2 = sv[tid + s];
            int i2 = si[tid + s];
            if (v2 > sv[tid] || (v2 == sv[tid] && i2 < si[tid])) { sv[tid] = v2; si[tid] = i2; }
        }
        __syncthreads();
    }
    if (tid == 0) {
        g_tokf[b] = (float)si[0];
        out[b * NSTEPS + step] = (float)si[0];
    }
}

extern "C" void kernel_launch(void* const* d_in, const int* in_sizes, int n_in,
                              void* d_out, int out_size) {
    // Insertion-order binding (confirmed by diagnostics):
    const float* inputs  = (const float*)d_in[0];
    const float* enc_Wih = (const float*)d_in[1];
    const float* enc_Whh = (const float*)d_in[2];
    const float* enc_bih = (const float*)d_in[3];
    const float* enc_bhh = (const float*)d_in[4];
    const float* dec_Wih = (const float*)d_in[5];
    const float* dec_Whh = (const float*)d_in[6];
    const float* dec_bih = (const float*)d_in[7];
    const float* dec_bhh = (const float*)d_in[8];
    const float* fc_W    = (const float*)d_in[9];
    const float* fc_b    = (const float*)d_in[10];
    float* out = (float*)d_out;

    prep_kernel<<<256, 256>>>(enc_bih, enc_bhh, dec_bih, dec_bhh, dec_Wih);

    // encoder: 512 sequential steps; x_t rows are strided (inputs is [B, T, I])
    for (int t = 0; t < Tn; t++)
        lstm_step<true><<<128, 512>>>(enc_Wih, inputs + (size_t)t * In, enc_Whh, t & 1);

    // decoder: 100 autoregressive steps
    for (int s = 0; s < NSTEPS; s++) {
        lstm_step<false><<<128, 512>>>(nullptr, nullptr, dec_Whh, s & 1);
        fc_partial<<<dim3(32, 4), 256>>>(fc_W, (s & 1) ^ 1);
        argmax_kernel<<<64, 128>>>(fc_b, out, s);
    }
}